// round 15
// baseline (speedup 1.0000x reference)
#include <cuda_runtime.h>
#include <cuda_bf16.h>

// ZBL screened nuclear repulsion:
//   expv = Dij/d * (Zi^p + Zj^p)
//   vij  = sum_k c[k] * exp(-a[k]*expv)
//   out  = segment_sum(vij, idx_i)   (idx_i sorted)
//
// R15: depth-2 software pipeline on the champion skeleton.
//   stage k+2: idx stream loads in flight
//   stage k+1: Z gathers in flight (issued from idx that arrived last iter)
//   stage k  : consume gather results (landed a full iteration ago),
//              MUFU z^p, FMA, merge, warp scan, boundary atomics.
// Removes the ~250-600cyc gather hop from the per-iteration critical chain
// (R14 issue=52% == half the slots stalled on exactly that chain).
// Front-batch depth per iteration unchanged (11-14 LDGs, queue-safe).

#define EPT   4
#define TPB   256
#define ITERS 4

__device__ __forceinline__ float ex2(float x) {
    float y;
    asm("ex2.approx.f32 %0, %1;" : "=f"(y) : "f"(x));
    return y;
}
__device__ __forceinline__ float lg2(float x) {
    float y;
    asm("lg2.approx.f32 %0, %1;" : "=f"(y) : "f"(x));
    return y;
}

// ---------------------------------------------------------------------------
__global__ __launch_bounds__(TPB)
void zbl_main_kernel(const float4* __restrict__ Dij4,
                     const int4*   __restrict__ idx_i4,
                     const int4*   __restrict__ idx_j4,
                     const int*    __restrict__ Z,
                     const float*  __restrict__ p_ptr,
                     const float*  __restrict__ d_ptr,
                     const float*  __restrict__ c_ptr,
                     const float*  __restrict__ a_ptr,
                     float*        __restrict__ out,
                     int V)   // number of 4-edge vectors
{
    const float p    = __ldg(p_ptr);
    const float invd = 1.0f / __ldg(d_ptr);
    const float c0 = __ldg(c_ptr + 0), c1 = __ldg(c_ptr + 1);
    const float c2 = __ldg(c_ptr + 2), c3 = __ldg(c_ptr + 3);
    // b_k = -a_k * log2(e) / d : folds exp->ex2 base change and 1/d
    const float NL2E = -1.4426950408889634f * invd;
    const float b0 = __ldg(a_ptr + 0) * NL2E, b1 = __ldg(a_ptr + 1) * NL2E;
    const float b2 = __ldg(a_ptr + 2) * NL2E, b3 = __ldg(a_ptr + 3) * NL2E;

    const int stride = gridDim.x * blockDim.x;
    const unsigned m = 0xFFFFFFFFu;
    const int lane = threadIdx.x & 31;

    // ---- pipeline prologue ----
    // stage 0 indices
    int  v0   = blockIdx.x * blockDim.x + threadIdx.x;
    bool val0 = (v0 < V);
    int4 ii0 = make_int4(0,0,0,0), jj0 = make_int4(0,0,0,0);
    if (val0) { ii0 = __ldcs(idx_i4 + v0); jj0 = __ldcs(idx_j4 + v0); }

    // stage 1 indices
    int  v1   = v0 + stride;
    bool val1 = (ITERS > 1) && (v1 < V);
    int4 ii1 = make_int4(0,0,0,0), jj1 = make_int4(0,0,0,0);
    if (val1) { ii1 = __ldcs(idx_i4 + v1); jj1 = __ldcs(idx_j4 + v1); }

    // stage 0 gathers (issued in prologue; consumed in iteration 0)
    int g0=0,g1=0,g2=0,g3=0,g4=0,g5=0,g6=0,g7=0;   // zi0-3, zj0-3
    if (val0) {
        g0 = __ldg(Z + ii0.x); g1 = __ldg(Z + ii0.y);
        g2 = __ldg(Z + ii0.z); g3 = __ldg(Z + ii0.w);
        g4 = __ldg(Z + jj0.x); g5 = __ldg(Z + jj0.y);
        g6 = __ldg(Z + jj0.z); g7 = __ldg(Z + jj0.w);
    }

    #pragma unroll 1
    for (int k = 0; k < ITERS; k++) {
        // ---- stage k+2: stream-load indices ----
        const int  v2   = v1 + stride;
        const bool val2 = (k + 2 < ITERS) && (v2 < V);
        int4 ii2 = make_int4(0,0,0,0), jj2 = make_int4(0,0,0,0);
        if (val2) { ii2 = __ldcs(idx_i4 + v2); jj2 = __ldcs(idx_j4 + v2); }

        // ---- stage k+1: issue Z gathers (roots arrived last iteration) ----
        int h0=0,h1=0,h2=0,h3=0,h4=0,h5=0,h6=0,h7=0;
        if (val1) {
            h0 = __ldg(Z + ii1.x); h1 = __ldg(Z + ii1.y);
            h2 = __ldg(Z + ii1.z); h3 = __ldg(Z + ii1.w);
            h4 = __ldg(Z + jj1.x); h5 = __ldg(Z + jj1.y);
            h6 = __ldg(Z + jj1.z); h7 = __ldg(Z + jj1.w);
        }

        // ---- stage k: consume (gathers issued a full iteration ago) ----
        int   cur = -1;     // pending segment id (tail)
        float acc = 0.0f;   // pending segment sum
        if (val0) {
            const float4 dd = __ldcs(Dij4 + v0);

            // z^p via MUFU: ex2(p*lg2 z); z=0 -> -inf -> 0 = pow(0,p)
            const float fi0 = ex2(p * lg2((float)g0));
            const float fi1 = ex2(p * lg2((float)g1));
            const float fi2 = ex2(p * lg2((float)g2));
            const float fi3 = ex2(p * lg2((float)g3));
            const float fj0 = ex2(p * lg2((float)g4));
            const float fj1 = ex2(p * lg2((float)g5));
            const float fj2 = ex2(p * lg2((float)g6));
            const float fj3 = ex2(p * lg2((float)g7));

            const float e0 = dd.x * (fi0 + fj0);
            const float e1 = dd.y * (fi1 + fj1);
            const float e2 = dd.z * (fi2 + fj2);
            const float e3 = dd.w * (fi3 + fj3);

            const float w0 = c0*ex2(b0*e0) + c1*ex2(b1*e0) + c2*ex2(b2*e0) + c3*ex2(b3*e0);
            const float w1 = c0*ex2(b0*e1) + c1*ex2(b1*e1) + c2*ex2(b2*e1) + c3*ex2(b3*e1);
            const float w2 = c0*ex2(b0*e2) + c1*ex2(b1*e2) + c2*ex2(b2*e2) + c3*ex2(b3*e2);
            const float w3 = c0*ex2(b0*e3) + c1*ex2(b1*e3) + c2*ex2(b2*e3) + c3*ex2(b3*e3);

            // sequential merge of the 4 sorted edges; flush interior runs
            cur = ii0.x; acc = w0;
            if (ii0.y == cur) acc += w1; else { atomicAdd(out + cur, acc); cur = ii0.y; acc = w1; }
            if (ii0.z == cur) acc += w2; else { atomicAdd(out + cur, acc); cur = ii0.z; acc = w2; }
            if (ii0.w == cur) acc += w3; else { atomicAdd(out + cur, acc); cur = ii0.w; acc = w3; }
        }

        // ---- warp-segmented inclusive scan over the pending tails ----
        // Edges sorted by idx_i; equal tail ids are contiguous across lanes.
        // Invalid lanes carry cur=-1 and are excluded by the cur>=0 guard.
        #pragma unroll
        for (int o = 1; o < 32; o <<= 1) {
            const float vv = __shfl_up_sync(m, acc, o);
            const int   ss = __shfl_up_sync(m, cur, o);
            if (lane >= o && ss == cur) acc += vv;
        }
        const int nxt = __shfl_down_sync(m, cur, 1);
        if (cur >= 0 && (lane == 31 || nxt != cur)) {
            atomicAdd(out + cur, acc);
        }

        // ---- rotate pipeline ----
        v0 = v1; val0 = val1; ii0 = ii1;             // jj0 dead after gathers
        v1 = v2; val1 = val2; ii1 = ii2; jj1 = jj2;
        g0 = h0; g1 = h1; g2 = h2; g3 = h3;
        g4 = h4; g5 = h5; g6 = h6; g7 = h7;
    }
}

// ---------------------------------------------------------------------------
// Tail kernel: handles E % 4 leftover edges (0 for this shape, but correct
// in general).
__global__ void zbl_tail_kernel(const float* __restrict__ Dij,
                                const int*   __restrict__ idx_i,
                                const int*   __restrict__ idx_j,
                                const int*   __restrict__ Z,
                                const float* __restrict__ p_ptr,
                                const float* __restrict__ d_ptr,
                                const float* __restrict__ c_ptr,
                                const float* __restrict__ a_ptr,
                                float*       __restrict__ out,
                                int start, int E)
{
    const float p    = __ldg(p_ptr);
    const float invd = 1.0f / __ldg(d_ptr);
    const float NL2E = -1.4426950408889634f * invd;
    const int e = start + blockIdx.x * blockDim.x + threadIdx.x;
    if (e < E) {
        const int   si = __ldg(idx_i + e);
        const int   sj = __ldg(idx_j + e);
        const float zpi = ex2(p * lg2((float)__ldg(Z + si)));
        const float zpj = ex2(p * lg2((float)__ldg(Z + sj)));
        const float ev  = __ldg(Dij + e) * (zpi + zpj);
        float vsum = 0.0f;
        #pragma unroll
        for (int k = 0; k < 4; k++)
            vsum += __ldg(c_ptr + k) * ex2(__ldg(a_ptr + k) * NL2E * ev);
        atomicAdd(out + si, vsum);
    }
}

// ---------------------------------------------------------------------------
extern "C" void kernel_launch(void* const* d_in, const int* in_sizes, int n_in,
                              void* d_out, int out_size)
{
    const int*   Z     = (const int*)  d_in[0];
    const float* Dij   = (const float*)d_in[1];
    const int*   idx_i = (const int*)  d_in[2];
    const int*   idx_j = (const int*)  d_in[3];
    const float* p_ptr = (const float*)d_in[4];
    const float* d_ptr = (const float*)d_in[5];
    const float* c_ptr = (const float*)d_in[6];
    const float* a_ptr = (const float*)d_in[7];
    float* out = (float*)d_out;

    const int E = in_sizes[1];
    const int V = E / 4;            // full 4-edge vectors
    const int tail_start = V * 4;

    // 1) zero the poisoned output (graph-capturable memset node)
    cudaMemsetAsync(out, 0, (size_t)out_size * sizeof(float));

    // 2) depth-2 pipelined main kernel
    {
        const long long threads_needed = ((long long)V + ITERS - 1) / ITERS;
        const int blocks = (int)((threads_needed + TPB - 1) / TPB);
        zbl_main_kernel<<<blocks, TPB>>>(
            reinterpret_cast<const float4*>(Dij),
            reinterpret_cast<const int4*>(idx_i),
            reinterpret_cast<const int4*>(idx_j),
            Z, p_ptr, d_ptr, c_ptr, a_ptr, out, V);
    }

    // 3) leftover edges (E % 4), if any
    if (tail_start < E) {
        const int n = E - tail_start;
        zbl_tail_kernel<<<(n + 63) / 64, 64>>>(Dij, idx_i, idx_j, Z,
                                               p_ptr, d_ptr, c_ptr, a_ptr,
                                               out, tail_start, E);
    }
}

// round 16
// speedup vs baseline: 1.0270x; 1.0270x over previous
#include <cuda_runtime.h>
#include <cuda_bf16.h>

// ZBL screened nuclear repulsion — FINAL champion (reproduced at 68.1us):
//   expv = Dij/d * (Zi^p + Zj^p)
//   vij  = sum_k c[k] * exp(-a[k]*expv)
//   out  = segment_sum(vij, idx_i)   (idx_i sorted)
//
// Converged architecture (14 measured rounds):
//  - EPT=4 edges/thread, float4/int4 streaming loads (.cs evict-first).
//    Deeper front-batching (EPT=8) overflows the ~248-entry l1tex
//    wavefront queue: measured 2x regression.
//  - ITERS=4 fixed-trip loop, depth-1 pipeline: next iteration's idx
//    vectors prefetched before this iteration's dependent work. Depth-2
//    (gathers prefetched too) costs 61 regs -> 45% occ -> 75us: worse.
//  - z^p on MUFU (ex2(p*lg2 z)); 1/d folded into exp coefficients.
//    Module-global scratch tables for z^p regress 1.5x (measured twice).
//  - Sorted segment-sum: per-thread run merge + warp-segmented shuffle
//    scan; one atomicAdd per warp-run boundary.
//  - 40 regs / TPB=256: optimum of the measured ILP/occupancy curve
//    (32r/88%:86us, 40r/66%:66us, 48r/55%:69us, 61r/45%:75us).
// Binder: l1tex wavefront issue for the 16M random Z[idx_j] lanes
// (~53us of the 66us main kernel). No further lever in this formulation.

#define EPT   4
#define TPB   256
#define ITERS 4

__device__ __forceinline__ float ex2(float x) {
    float y;
    asm("ex2.approx.f32 %0, %1;" : "=f"(y) : "f"(x));
    return y;
}
__device__ __forceinline__ float lg2(float x) {
    float y;
    asm("lg2.approx.f32 %0, %1;" : "=f"(y) : "f"(x));
    return y;
}

// ---------------------------------------------------------------------------
__global__ __launch_bounds__(TPB)
void zbl_main_kernel(const float4* __restrict__ Dij4,
                     const int4*   __restrict__ idx_i4,
                     const int4*   __restrict__ idx_j4,
                     const int*    __restrict__ Z,
                     const float*  __restrict__ p_ptr,
                     const float*  __restrict__ d_ptr,
                     const float*  __restrict__ c_ptr,
                     const float*  __restrict__ a_ptr,
                     float*        __restrict__ out,
                     int V)   // number of 4-edge vectors
{
    const float p    = __ldg(p_ptr);
    const float invd = 1.0f / __ldg(d_ptr);
    const float c0 = __ldg(c_ptr + 0), c1 = __ldg(c_ptr + 1);
    const float c2 = __ldg(c_ptr + 2), c3 = __ldg(c_ptr + 3);
    // b_k = -a_k * log2(e) / d : folds exp->ex2 base change and 1/d
    const float NL2E = -1.4426950408889634f * invd;
    const float b0 = __ldg(a_ptr + 0) * NL2E, b1 = __ldg(a_ptr + 1) * NL2E;
    const float b2 = __ldg(a_ptr + 2) * NL2E, b3 = __ldg(a_ptr + 3) * NL2E;

    const int stride = gridDim.x * blockDim.x;
    int v = blockIdx.x * blockDim.x + threadIdx.x;

    const unsigned m = 0xFFFFFFFFu;
    const int lane = threadIdx.x & 31;

    // ---- prologue: prefetch iteration 0's index vectors (gather roots) ----
    bool valid = (v < V);
    int4 ii = make_int4(0, 0, 0, 0);
    int4 jj = make_int4(0, 0, 0, 0);
    if (valid) {
        ii = __ldcs(idx_i4 + v);
        jj = __ldcs(idx_j4 + v);
    }

    #pragma unroll 1
    for (int k = 0; k < ITERS; k++) {
        int   cur = -1;     // pending segment id (tail)
        float acc = 0.0f;   // pending segment sum

        // next iteration's index prefetch (issued before this iteration's
        // dependent work so the DRAM hop overlaps the gather+math+scan)
        const int  vn     = v + stride;
        const bool nvalid = (k + 1 < ITERS) && (vn < V);
        int4 ii_n = make_int4(0, 0, 0, 0);
        int4 jj_n = make_int4(0, 0, 0, 0);
        if (nvalid) {
            ii_n = __ldcs(idx_i4 + vn);
            jj_n = __ldcs(idx_j4 + vn);
        }

        if (valid) {
            // ---- Dij load: independent of the gather chain, self-hiding ----
            const float4 dd = __ldcs(Dij4 + v);

            // ---- 8 independent scalar gathers from the input Z array ----
            const int zi0 = __ldg(Z + ii.x), zi1 = __ldg(Z + ii.y);
            const int zi2 = __ldg(Z + ii.z), zi3 = __ldg(Z + ii.w);
            const int zj0 = __ldg(Z + jj.x), zj1 = __ldg(Z + jj.y);
            const int zj2 = __ldg(Z + jj.z), zj3 = __ldg(Z + jj.w);

            // ---- z^p via MUFU: ex2(p*lg2 z); z=0 -> -inf -> 0 = pow(0,p) ----
            const float fi0 = ex2(p * lg2((float)zi0));
            const float fi1 = ex2(p * lg2((float)zi1));
            const float fi2 = ex2(p * lg2((float)zi2));
            const float fi3 = ex2(p * lg2((float)zi3));
            const float fj0 = ex2(p * lg2((float)zj0));
            const float fj1 = ex2(p * lg2((float)zj1));
            const float fj2 = ex2(p * lg2((float)zj2));
            const float fj3 = ex2(p * lg2((float)zj3));

            const float e0 = dd.x * (fi0 + fj0);
            const float e1 = dd.y * (fi1 + fj1);
            const float e2 = dd.z * (fi2 + fj2);
            const float e3 = dd.w * (fi3 + fj3);

            const float v0 = c0*ex2(b0*e0) + c1*ex2(b1*e0) + c2*ex2(b2*e0) + c3*ex2(b3*e0);
            const float v1 = c0*ex2(b0*e1) + c1*ex2(b1*e1) + c2*ex2(b2*e1) + c3*ex2(b3*e1);
            const float v2 = c0*ex2(b0*e2) + c1*ex2(b1*e2) + c2*ex2(b2*e2) + c3*ex2(b3*e2);
            const float v3 = c0*ex2(b0*e3) + c1*ex2(b1*e3) + c2*ex2(b2*e3) + c3*ex2(b3*e3);

            // ---- sequential merge of the 4 sorted edges; flush interior runs ----
            cur = ii.x; acc = v0;
            if (ii.y == cur) acc += v1; else { atomicAdd(out + cur, acc); cur = ii.y; acc = v1; }
            if (ii.z == cur) acc += v2; else { atomicAdd(out + cur, acc); cur = ii.z; acc = v2; }
            if (ii.w == cur) acc += v3; else { atomicAdd(out + cur, acc); cur = ii.w; acc = v3; }
        }

        // ---- warp-segmented inclusive scan over the pending tails ----
        // Edges sorted by idx_i; equal tail ids are contiguous across lanes.
        // Invalid lanes carry cur=-1 and are excluded by the cur>=0 guard.
        #pragma unroll
        for (int o = 1; o < 32; o <<= 1) {
            const float vv = __shfl_up_sync(m, acc, o);
            const int   ss = __shfl_up_sync(m, cur, o);
            if (lane >= o && ss == cur) acc += vv;
        }
        const int nxt = __shfl_down_sync(m, cur, 1);
        if (cur >= 0 && (lane == 31 || nxt != cur)) {
            atomicAdd(out + cur, acc);
        }

        // ---- rotate pipeline ----
        v = vn; valid = nvalid;
        ii = ii_n; jj = jj_n;
    }
}

// ---------------------------------------------------------------------------
// Tail kernel: handles E % 4 leftover edges (0 for this shape, but correct
// in general).
__global__ void zbl_tail_kernel(const float* __restrict__ Dij,
                                const int*   __restrict__ idx_i,
                                const int*   __restrict__ idx_j,
                                const int*   __restrict__ Z,
                                const float* __restrict__ p_ptr,
                                const float* __restrict__ d_ptr,
                                const float* __restrict__ c_ptr,
                                const float* __restrict__ a_ptr,
                                float*       __restrict__ out,
                                int start, int E)
{
    const float p    = __ldg(p_ptr);
    const float invd = 1.0f / __ldg(d_ptr);
    const float NL2E = -1.4426950408889634f * invd;
    const int e = start + blockIdx.x * blockDim.x + threadIdx.x;
    if (e < E) {
        const int   si = __ldg(idx_i + e);
        const int   sj = __ldg(idx_j + e);
        const float zpi = ex2(p * lg2((float)__ldg(Z + si)));
        const float zpj = ex2(p * lg2((float)__ldg(Z + sj)));
        const float ev  = __ldg(Dij + e) * (zpi + zpj);
        float vsum = 0.0f;
        #pragma unroll
        for (int k = 0; k < 4; k++)
            vsum += __ldg(c_ptr + k) * ex2(__ldg(a_ptr + k) * NL2E * ev);
        atomicAdd(out + si, vsum);
    }
}

// ---------------------------------------------------------------------------
extern "C" void kernel_launch(void* const* d_in, const int* in_sizes, int n_in,
                              void* d_out, int out_size)
{
    const int*   Z     = (const int*)  d_in[0];
    const float* Dij   = (const float*)d_in[1];
    const int*   idx_i = (const int*)  d_in[2];
    const int*   idx_j = (const int*)  d_in[3];
    const float* p_ptr = (const float*)d_in[4];
    const float* d_ptr = (const float*)d_in[5];
    const float* c_ptr = (const float*)d_in[6];
    const float* a_ptr = (const float*)d_in[7];
    float* out = (float*)d_out;

    const int E = in_sizes[1];
    const int V = E / 4;            // full 4-edge vectors
    const int tail_start = V * 4;

    // 1) zero the poisoned output (graph-capturable memset node; must
    //    precede the atomics, so it cannot be overlapped with the kernel)
    cudaMemsetAsync(out, 0, (size_t)out_size * sizeof(float));

    // 2) pipelined main kernel: each thread handles ITERS vectors grid-stride
    {
        const long long threads_needed = ((long long)V + ITERS - 1) / ITERS;
        const int blocks = (int)((threads_needed + TPB - 1) / TPB);
        zbl_main_kernel<<<blocks, TPB>>>(
            reinterpret_cast<const float4*>(Dij),
            reinterpret_cast<const int4*>(idx_i),
            reinterpret_cast<const int4*>(idx_j),
            Z, p_ptr, d_ptr, c_ptr, a_ptr, out, V);
    }

    // 3) leftover edges (E % 4), if any
    if (tail_start < E) {
        const int n = E - tail_start;
        zbl_tail_kernel<<<(n + 63) / 64, 64>>>(Dij, idx_i, idx_j, Z,
                                               p_ptr, d_ptr, c_ptr, a_ptr,
                                               out, tail_start, E);
    }
}